// round 14
// baseline (speedup 1.0000x reference)
#include <cuda_runtime.h>

// Problem constants
#define NMAX   50000
#define EMAX   800000
#define IN_DIM 128
#define H1DIM  128   // HEADS*HID
#define NHEADS 4
#define HID    32
#define OUTD   64
#define SLOPE  0.2f

#define SCAN_CHUNK 1024
#define MAX_PARTS  64          // ceil(50000/1024)=49 < 64

// ---------------- scratch (static __device__ globals; no allocation) ----------
__device__ int   g_is64;
__device__ int   g_deg[NMAX];
__device__ int   g_off[NMAX];
__device__ int   g_cur[NMAX];
__device__ int   g_part[MAX_PARTS];
__device__ int   g_csr [EMAX];    // src per CSR slot
__device__ int   g_csrd[EMAX];    // dst per CSR slot
__device__ float g_w1  [EMAX * NHEADS];  // per-edge softmax numerators, layer 1
__device__ float g_w2  [EMAX];           // per-edge softmax numerators, layer 2
__device__ float g_h1  [NMAX * H1DIM];
__device__ float g_als1[NMAX * NHEADS];
__device__ float g_ald1[NMAX * NHEADS];
__device__ float g_out1[NMAX * H1DIM];
__device__ float g_h2  [NMAX * OUTD];
__device__ float g_als2[NMAX];
__device__ float g_ald2[NMAX];

// ---------------- edge dtype detect + access --------------------------------
__global__ void k_detect(const unsigned int* __restrict__ p) {
    unsigned v = p[threadIdx.x * 2 + 1];
    unsigned all0 = __all_sync(0xffffffffu, v == 0u);
    if (threadIdx.x == 0) g_is64 = (int)all0;
}

__device__ __forceinline__ int edge_at(const void* p, long long i) {
    if (g_is64) return (int)((const long long*)p)[i];
    return ((const int*)p)[i];
}

// ---------------- CSR build --------------------------------------------------
__global__ void k_zero(int n) {
    int i = blockIdx.x * blockDim.x + threadIdx.x;
    if (i < n) g_deg[i] = 0;
}

__global__ void k_count(const void* __restrict__ ei, int e) {
    int i = blockIdx.x * blockDim.x + threadIdx.x;
    if (i < e) {
        int d = edge_at(ei, (long long)e + i);   // dst row
        atomicAdd(&g_deg[d], 1);
    }
}

// ---- phase 1: per-chunk (1024 elems) sums ----------------------------------
__global__ void k_scan_partial(int n) {
    __shared__ int sm[8];
    int b = blockIdx.x, t = threadIdx.x;
    int base = b * SCAN_CHUNK + t * 4;
    int s = 0;
#pragma unroll
    for (int j = 0; j < 4; j++) {
        int i = base + j;
        if (i < n) s += g_deg[i];
    }
#pragma unroll
    for (int o = 16; o > 0; o >>= 1) s += __shfl_down_sync(0xffffffffu, s, o);
    if ((t & 31) == 0) sm[t >> 5] = s;
    __syncthreads();
    if (t < 8) {
        int v = sm[t];
#pragma unroll
        for (int o = 4; o > 0; o >>= 1) v += __shfl_down_sync(0xffu, v, o);
        if (t == 0) g_part[b] = v;
    }
}

// ---- phase 2: exclusive scan of chunk sums ---------------------------------
__global__ void k_scan_part(int nb) {
    __shared__ int sm[MAX_PARTS];
    int t = threadIdx.x;
    int v = (t < nb) ? g_part[t] : 0;
    sm[t] = v;
    __syncthreads();
#pragma unroll
    for (int d = 1; d < MAX_PARTS; d <<= 1) {
        int x = (t >= d) ? sm[t - d] : 0;
        __syncthreads();
        sm[t] += x;
        __syncthreads();
    }
    if (t < nb) g_part[t] = sm[t] - v;     // exclusive
}

// ---- phase 3: re-scan chunk with offset, write g_off / g_cur ---------------
__global__ void k_scan_final(int n) {
    __shared__ int sm[256];
    int b = blockIdx.x, t = threadIdx.x;
    int base = b * SCAN_CHUNK + t * 4;
    int v[4];
    int s = 0;
#pragma unroll
    for (int j = 0; j < 4; j++) {
        int i = base + j;
        v[j] = (i < n) ? g_deg[i] : 0;
        s += v[j];
    }
    sm[t] = s;
    __syncthreads();
#pragma unroll
    for (int d = 1; d < 256; d <<= 1) {
        int x = (t >= d) ? sm[t - d] : 0;
        __syncthreads();
        sm[t] += x;
        __syncthreads();
    }
    int run = g_part[b] + ((t > 0) ? sm[t - 1] : 0);
#pragma unroll
    for (int j = 0; j < 4; j++) {
        int i = base + j;
        if (i < n) {
            g_off[i] = run;
            g_cur[i] = run;
            run += v[j];
        }
    }
}

__global__ void k_scatter(const void* __restrict__ ei, int e) {
    int i = blockIdx.x * blockDim.x + threadIdx.x;
    if (i < e) {
        int s = edge_at(ei, i);
        int d = edge_at(ei, (long long)e + i);
        int pos = atomicAdd(&g_cur[d], 1);
        g_csr[pos]  = s;
        g_csrd[pos] = d;
    }
}

// ---------------- fp32 tiled GEMM, K = 128 fixed, fused alpha epilogue -------
// C[M,BN] = A[M,128] @ B[128,BN]; als[r,h] = C[r,:].a_s chunks, likewise ald.
// 256 threads, BM=64, BK=32. Row r is held by TX consecutive lanes.
template <int BN, int H>
__device__ __forceinline__ void gemm128(const float* __restrict__ A,
                                        const float* __restrict__ B,
                                        float* __restrict__ C,
                                        const float* __restrict__ a_s,
                                        const float* __restrict__ a_d,
                                        float* __restrict__ als,
                                        float* __restrict__ ald, int M) {
    constexpr int K = 128, BM = 64, BK = 32;
    constexpr int TX = BN / 4;       // 32 (BN=128) or 16 (BN=64)
    constexpr int TY = 256 / TX;     // 8 or 16
    constexpr int TM = BM / TY;      // 8 or 4
    constexpr int RL = TX / H;       // lanes reduced per head: 8 (L1) / 16 (L2)
    __shared__ float As[BM][BK];
    __shared__ float Bs[BK][BN];
    int tid = threadIdx.x;
    int tx = tid % TX, ty = tid / TX;
    int row0 = blockIdx.x * BM;

    float acc[TM][4];
#pragma unroll
    for (int i = 0; i < TM; i++) { acc[i][0] = acc[i][1] = acc[i][2] = acc[i][3] = 0.f; }

    for (int kt = 0; kt < K; kt += BK) {
#pragma unroll
        for (int j = 0; j < (BM * BK) / 256; j++) {
            int idx = tid + j * 256;
            int r = idx >> 5;
            int kk = idx & 31;
            int grow = row0 + r;
            As[r][kk] = (grow < M) ? A[(long long)grow * K + kt + kk] : 0.f;
        }
#pragma unroll
        for (int j = 0; j < (BK * BN) / 256; j++) {
            int idx = tid + j * 256;
            int kk = idx / BN;
            int nn = idx % BN;
            Bs[kk][nn] = B[(kt + kk) * BN + nn];
        }
        __syncthreads();
#pragma unroll
        for (int kk = 0; kk < BK; kk++) {
            float4 b4 = *(const float4*)&Bs[kk][tx * 4];
#pragma unroll
            for (int i = 0; i < TM; i++) {
                float a = As[ty + i * TY][kk];
                acc[i][0] = fmaf(a, b4.x, acc[i][0]);
                acc[i][1] = fmaf(a, b4.y, acc[i][1]);
                acc[i][2] = fmaf(a, b4.z, acc[i][2]);
                acc[i][3] = fmaf(a, b4.w, acc[i][3]);
            }
        }
        __syncthreads();
    }

    // epilogue: store C + fused alpha dot products
    float4 s4 = *(const float4*)&a_s[tx * 4];
    float4 d4 = *(const float4*)&a_d[tx * 4];
#pragma unroll
    for (int i = 0; i < TM; i++) {
        int r = row0 + ty + i * TY;
        if (r < M) {
            float4 o = make_float4(acc[i][0], acc[i][1], acc[i][2], acc[i][3]);
            *(float4*)&C[(long long)r * BN + tx * 4] = o;
            float ps = o.x * s4.x + o.y * s4.y + o.z * s4.z + o.w * s4.w;
            float pd = o.x * d4.x + o.y * d4.y + o.z * d4.z + o.w * d4.w;
#pragma unroll
            for (int off = RL / 2; off > 0; off >>= 1) {
                ps += __shfl_xor_sync(0xffffffffu, ps, off);
                pd += __shfl_xor_sync(0xffffffffu, pd, off);
            }
            if ((tx % RL) == 0) {
                int head = tx / RL;
                als[r * H + head] = ps;
                ald[r * H + head] = pd;
            }
        }
    }
}

__global__ void k_gemm1(const float* __restrict__ x, const float* __restrict__ W1,
                        const float* __restrict__ a_s, const float* __restrict__ a_d, int M) {
    gemm128<H1DIM, NHEADS>(x, W1, g_h1, a_s, a_d, g_als1, g_ald1, M);
}
__global__ void k_gemm2(const float* __restrict__ W2,
                        const float* __restrict__ a_s, const float* __restrict__ a_d, int M) {
    gemm128<OUTD, 1>(g_out1, W2, g_h2, a_s, a_d, g_als2, g_ald2, M);
}

__device__ __forceinline__ float lrelu(float e) { return e > 0.f ? e : SLOPE * e; }

// ---------------- edge-parallel softmax-numerator precompute -----------------
// Each thread computes DISTINCT edge weights -> full MUFU lane utilization.
__global__ void k_w1(int e) {
    int i = blockIdx.x * blockDim.x + threadIdx.x;
    if (i >= e) return;
    int s = g_csr[i], d = g_csrd[i];
    float4 as = *(const float4*)&g_als1[s * 4];
    float4 ad = *(const float4*)&g_ald1[d * 4];
    float4 w;
    w.x = __expf(lrelu(as.x + ad.x));
    w.y = __expf(lrelu(as.y + ad.y));
    w.z = __expf(lrelu(as.z + ad.z));
    w.w = __expf(lrelu(as.w + ad.w));
    *(float4*)&g_w1[(long long)i * 4] = w;
}

__global__ void k_w2(int e) {
    int i = blockIdx.x * blockDim.x + threadIdx.x;
    if (i >= e) return;
    int s = g_csr[i], d = g_csrd[i];
    g_w2[i] = __expf(lrelu(g_als2[s] + g_ald2[d]));
}

// ---------------- layer 1 aggregation: warp per dst, lane = channel ----------
__global__ void k_agg1(const float* __restrict__ b1, int n) {
    int w = (blockIdx.x * blockDim.x + threadIdx.x) >> 5;
    int lane = threadIdx.x & 31;
    if (w >= n) return;

    float4 ad4 = *(const float4*)&g_ald1[w * 4];
    float4 as4 = *(const float4*)&g_als1[w * 4];

    float acc[4], z[4];
    // self loop
    {
        float wt0 = __expf(lrelu(as4.x + ad4.x));
        float wt1 = __expf(lrelu(as4.y + ad4.y));
        float wt2 = __expf(lrelu(as4.z + ad4.z));
        float wt3 = __expf(lrelu(as4.w + ad4.w));
        z[0] = wt0; z[1] = wt1; z[2] = wt2; z[3] = wt3;
        const float* hr = &g_h1[(long long)w * 128 + lane];
        acc[0] = wt0 * hr[0];
        acc[1] = wt1 * hr[32];
        acc[2] = wt2 * hr[64];
        acc[3] = wt3 * hr[96];
    }

    int p = g_off[w];
    int end = p + g_deg[w];
    int s = (p < end) ? g_csr[p] : 0;
    for (; p < end; p++) {
        int sc = s;
        if (p + 1 < end) s = g_csr[p + 1];           // prefetch next src id
        float4 w4 = *(const float4*)&g_w1[(long long)p * 4];
        const float* hr = &g_h1[(long long)sc * 128 + lane];
        z[0] += w4.x; z[1] += w4.y; z[2] += w4.z; z[3] += w4.w;
        acc[0] = fmaf(w4.x, hr[0],  acc[0]);
        acc[1] = fmaf(w4.y, hr[32], acc[1]);
        acc[2] = fmaf(w4.z, hr[64], acc[2]);
        acc[3] = fmaf(w4.w, hr[96], acc[3]);
    }
#pragma unroll
    for (int h = 0; h < 4; h++) {
        float v = acc[h] / (z[h] + 1e-16f) + b1[h * 32 + lane];
        g_out1[(long long)w * 128 + h * 32 + lane] = v > 0.f ? v : 0.f;
    }
}

// ---------------- layer 2 aggregation: warp per dst, lane covers c, c+32 -----
__global__ void k_agg2(const float* __restrict__ b2, float* __restrict__ out, int n) {
    int w = (blockIdx.x * blockDim.x + threadIdx.x) >> 5;
    int lane = threadIdx.x & 31;
    if (w >= n) return;

    float wt = __expf(lrelu(g_als2[w] + g_ald2[w]));  // self loop
    float z = wt;
    float acc0 = wt * g_h2[(long long)w * 64 + lane];
    float acc1 = wt * g_h2[(long long)w * 64 + 32 + lane];

    int p = g_off[w];
    int end = p + g_deg[w];
    int s = (p < end) ? g_csr[p] : 0;
    for (; p < end; p++) {
        int sc = s;
        if (p + 1 < end) s = g_csr[p + 1];
        float wt2 = g_w2[p];
        const float* hr = &g_h2[(long long)sc * 64 + lane];
        z += wt2;
        acc0 = fmaf(wt2, hr[0],  acc0);
        acc1 = fmaf(wt2, hr[32], acc1);
    }
    float inv = 1.f / (z + 1e-16f);
    out[(long long)w * 64 + lane]      = acc0 * inv + b2[lane];
    out[(long long)w * 64 + 32 + lane] = acc1 * inv + b2[32 + lane];
}

// ---------------- launch -----------------------------------------------------
extern "C" void kernel_launch(void* const* d_in, const int* in_sizes, int n_in,
                              void* d_out, int out_size) {
    const float* x   = (const float*)d_in[0];
    const void*  ei  = d_in[1];                    // edge_index [2,E], int64 or int32
    const float* W1  = (const float*)d_in[3];
    const float* as1 = (const float*)d_in[4];
    const float* ad1 = (const float*)d_in[5];
    const float* b1  = (const float*)d_in[6];
    const float* W2  = (const float*)d_in[7];
    const float* as2 = (const float*)d_in[8];
    const float* ad2 = (const float*)d_in[9];
    const float* b2  = (const float*)d_in[10];
    float* out = (float*)d_out;

    int n = in_sizes[0] / IN_DIM;                  // 50000
    int e = in_sizes[1] / 2;                       // 800000
    int nb = (n + SCAN_CHUNK - 1) / SCAN_CHUNK;    // 49

    // edge dtype detection (probe odd 32-bit words)
    k_detect<<<1, 32>>>((const unsigned int*)ei);

    // CSR build over dst (multi-block 3-phase scan)
    k_zero<<<(n + 255) / 256, 256>>>(n);
    k_count<<<(e + 255) / 256, 256>>>(ei, e);
    k_scan_partial<<<nb, 256>>>(n);
    k_scan_part<<<1, MAX_PARTS>>>(nb);
    k_scan_final<<<nb, 256>>>(n);
    k_scatter<<<(e + 255) / 256, 256>>>(ei, e);

    // layer 1
    k_gemm1<<<(n + 63) / 64, 256>>>(x, W1, as1, ad1, n);
    k_w1<<<(e + 255) / 256, 256>>>(e);
    k_agg1<<<(n + 7) / 8, 256>>>(b1, n);

    // layer 2
    k_gemm2<<<(n + 63) / 64, 256>>>(W2, as2, ad2, n);
    k_w2<<<(e + 255) / 256, 256>>>(e);
    k_agg2<<<(n + 7) / 8, 256>>>(b2, out, n);
}